// round 11
// baseline (speedup 1.0000x reference)
#include <cuda_runtime.h>
#include <stdint.h>

// PHM embedding: out[tok, q*256+j] = sum_k a[k,p,q]*s[k,i,j]; p=t/12565, i=t%12565.
//   a:[4,4,4] f32 ; s:[4,12565,256] f32 ; out:[16384,1024] f32
//
// DRAM-byte reduction: bin tokens by i (99 bins of 128 rows) so duplicate /
// neighboring s rows are read temporally adjacent -> L2 dedups them. Reads
// drop from ~48MB (full s re-stream) to ~36.6MB compulsory. Main gather body
// is the proven R1 layout (4 tok x 64 lanes). Bin state self-cleans inside
// the main kernel (done-counter; last block of each bin re-zeros) so the
// 2-kernel graph is replay-invariant with no zeroing pass.

static constexpr int N_ROWS = 12565;   // VOCAB_PAD / 4
static constexpr int EV4    = 64;      // 256 f32 per s row = 64 float4
static constexpr int BINS   = 99;      // i >> 7
static constexpr int SLOTS  = 256;     // per-bin capacity (mean ~166, 7 sigma)
static constexpr int BLKS_PER_BIN = 64;   // 64 blocks x 4 tokens = 256 slots

__device__ int d_cnt[BINS];            // zero-init; zeroed by main each call
__device__ int d_done[BINS];           // zero-init; zeroed by main each call
__device__ int d_slot[BINS * SLOTS];

__global__ void build_buckets(const int* __restrict__ inp, int n_tok)
{
    const int tok = blockIdx.x * blockDim.x + threadIdx.x;
    if (tok >= n_tok) return;
    const int t = inp[tok];
    const int p = t / N_ROWS;                     // magic-number divide
    const int i = t - p * N_ROWS;
    const int bin = i >> 7;
    const int r = atomicAdd(&d_cnt[bin], 1);
    if (r < SLOTS)
        d_slot[bin * SLOTS + r] = tok | (p << 14) | (i << 16); // 14+2+14 bits
}

__device__ __forceinline__ void stg_stream(float4* p, float4 v, uint64_t pol) {
    asm volatile("st.global.L2::cache_hint.v4.f32 [%0], {%1,%2,%3,%4}, %5;"
                 :: "l"(p), "f"(v.x), "f"(v.y), "f"(v.z), "f"(v.w), "l"(pol)
                 : "memory");
}

__global__ void __launch_bounds__(256, 8)
phm_main(const float* __restrict__ a,
         const float4* __restrict__ s,
         float4* __restrict__ out)
{
    __shared__ int sh_cnt;
    const int bin = blockIdx.x >> 6;              // / BLKS_PER_BIN
    const int grp = blockIdx.x & (BLKS_PER_BIN - 1);

    if (threadIdx.x == 0) {
        const int c = d_cnt[bin];
        sh_cnt = c;
        // (c & 0) forces the cnt load to complete before the done-arrive,
        // so the last arriver may safely zero d_cnt (all 64 reads done).
        const int r = atomicAdd(&d_done[bin], 1 + (c & 0));
        if (r == BLKS_PER_BIN - 1) { d_cnt[bin] = 0; d_done[bin] = 0; }
    }
    __syncthreads();

    const int cnt = sh_cnt < SLOTS ? sh_cnt : SLOTS;
    const int lane = threadIdx.x & 63;            // float4 column
    const int tsub = threadIdx.x >> 6;            // token within block
    const int slot = grp * 4 + tsub;
    if (slot >= cnt) return;

    const int v   = d_slot[bin * SLOTS + slot];
    const int tok = v & 0x3FFF;
    const int p   = (v >> 14) & 3;
    const int i   = v >> 16;

    const float4* srow = s + (size_t)i * EV4 + lane;
    const float4 sv0 = __ldg(srow + 0 * N_ROWS * EV4);
    const float4 sv1 = __ldg(srow + 1 * N_ROWS * EV4);
    const float4 sv2 = __ldg(srow + 2 * N_ROWS * EV4);
    const float4 sv3 = __ldg(srow + 3 * N_ROWS * EV4);

    uint64_t pol_stream;
    asm volatile("createpolicy.fractional.L2::evict_first.b64 %0, 1.0;"
                 : "=l"(pol_stream));

    const float* ap = a + p * 4;                  // a[k,p,q] = a[k*16+p*4+q]
    float4* outp = out + (size_t)tok * 256 + lane;

#pragma unroll
    for (int q = 0; q < 4; q++) {
        const float c0 = __ldg(&ap[ 0 + q]);
        const float c1 = __ldg(&ap[16 + q]);
        const float c2 = __ldg(&ap[32 + q]);
        const float c3 = __ldg(&ap[48 + q]);
        float4 o;
        o.x = c0 * sv0.x + c1 * sv1.x + c2 * sv2.x + c3 * sv3.x;
        o.y = c0 * sv0.y + c1 * sv1.y + c2 * sv2.y + c3 * sv3.y;
        o.z = c0 * sv0.z + c1 * sv1.z + c2 * sv2.z + c3 * sv3.z;
        o.w = c0 * sv0.w + c1 * sv1.w + c2 * sv2.w + c3 * sv3.w;
        stg_stream(outp + q * EV4, o, pol_stream);
    }
}

extern "C" void kernel_launch(void* const* d_in, const int* in_sizes, int n_in,
                              void* d_out, int out_size)
{
    const int*    inp = (const int*)d_in[0];    // [8,2048] int32
    const float*  a   = (const float*)d_in[1];  // [4,4,4]
    const float4* s   = (const float4*)d_in[2]; // [4,12565,256] as float4
    float4*       out = (float4*)d_out;

    const int n_tok = in_sizes[0];              // 16384

    build_buckets<<<(n_tok + 255) / 256, 256>>>(inp, n_tok);
    phm_main<<<BINS * BLKS_PER_BIN, 256>>>(a, s, out);
}

// round 12
// speedup vs baseline: 1.2003x; 1.2003x over previous
#include <cuda_runtime.h>
#include <stdint.h>

// PHM embedding: out[tok, q*256 + j] = sum_k a[k,p,q] * s[k,i,j]
//   t = input[tok]; p = t / 12565; i = t % 12565
//   a: [4,4,4] (k,p,q) f32 ; s: [4,12565,256] f32 ; out: [16384,1024] f32
//
// MLP-8 layout (8 tok x 32 lanes, best measured kernel time) with
// st.global.wt output stores: write-through = no-write-allocate, so the
// 67MB store stream stops evicting s from L2 (duplicate-row reads hit)
// and no dirty-line drain remains between graph replays.

static constexpr int N_ROWS = 12565;   // VOCAB_PAD / 4
static constexpr int EV4    = 64;      // 256 f32 cols / 4 per float4
static constexpr int TOK_PER_BLK = 8;

__device__ __forceinline__ void stg_wt(float4* p, float4 v) {
    asm volatile("st.global.wt.v4.f32 [%0], {%1,%2,%3,%4};"
                 :: "l"(p), "f"(v.x), "f"(v.y), "f"(v.z), "f"(v.w)
                 : "memory");
}

__global__ void __launch_bounds__(256, 4)
phm_embed_kernel(const int* __restrict__ inp,
                 const float* __restrict__ a,
                 const float4* __restrict__ s,
                 float4* __restrict__ out,
                 int n_tok)
{
    const int lane = threadIdx.x & 31;        // first float4 column
    const int tsub = threadIdx.x >> 5;        // token within block (0..7)
    const int tok  = blockIdx.x * TOK_PER_BLK + tsub;
    if (tok >= n_tok) return;

    const int t = inp[tok];
    const int p = t / N_ROWS;                 // compile-time magic divide
    const int i = t - p * N_ROWS;

    const float4* srow = s + (size_t)i * EV4 + lane;

    // 8 independent loads front-batched: 4 k-rows x 2 column vectors.
    float4 svA0 = __ldg(srow + 0 * N_ROWS * EV4);
    float4 svB0 = __ldg(srow + 0 * N_ROWS * EV4 + 32);
    float4 svA1 = __ldg(srow + 1 * N_ROWS * EV4);
    float4 svB1 = __ldg(srow + 1 * N_ROWS * EV4 + 32);
    float4 svA2 = __ldg(srow + 2 * N_ROWS * EV4);
    float4 svB2 = __ldg(srow + 2 * N_ROWS * EV4 + 32);
    float4 svA3 = __ldg(srow + 3 * N_ROWS * EV4);
    float4 svB3 = __ldg(srow + 3 * N_ROWS * EV4 + 32);

    // a[k,p,q] = a[k*16 + p*4 + q]; broadcast loads, L1-resident.
    const float* ap = a + p * 4;

    float4* outp = out + (size_t)tok * 256 + lane;   // 256 float4 per token

#pragma unroll
    for (int q = 0; q < 4; q++) {
        const float c0 = __ldg(&ap[ 0 + q]);
        const float c1 = __ldg(&ap[16 + q]);
        const float c2 = __ldg(&ap[32 + q]);
        const float c3 = __ldg(&ap[48 + q]);

        float4 oA, oB;
        oA.x = c0 * svA0.x + c1 * svA1.x + c2 * svA2.x + c3 * svA3.x;
        oA.y = c0 * svA0.y + c1 * svA1.y + c2 * svA2.y + c3 * svA3.y;
        oA.z = c0 * svA0.z + c1 * svA1.z + c2 * svA2.z + c3 * svA3.z;
        oA.w = c0 * svA0.w + c1 * svA1.w + c2 * svA2.w + c3 * svA3.w;

        oB.x = c0 * svB0.x + c1 * svB1.x + c2 * svB2.x + c3 * svB3.x;
        oB.y = c0 * svB0.y + c1 * svB1.y + c2 * svB2.y + c3 * svB3.y;
        oB.z = c0 * svB0.z + c1 * svB1.z + c2 * svB2.z + c3 * svB3.z;
        oB.w = c0 * svB0.w + c1 * svB1.w + c2 * svB2.w + c3 * svB3.w;

        stg_wt(outp + q * EV4,      oA);
        stg_wt(outp + q * EV4 + 32, oB);
    }
}

extern "C" void kernel_launch(void* const* d_in, const int* in_sizes, int n_in,
                              void* d_out, int out_size)
{
    const int*    inp = (const int*)d_in[0];    // [8,2048] int32
    const float*  a   = (const float*)d_in[1];  // [4,4,4]
    const float4* s   = (const float4*)d_in[2]; // [4,12565,256] f32 as float4
    float4*       out = (float4*)d_out;

    const int n_tok = in_sizes[0];              // 16384
    const int grid  = (n_tok + TOK_PER_BLK - 1) / TOK_PER_BLK;
    phm_embed_kernel<<<grid, 256>>>(inp, a, s, out, n_tok);
}

// round 13
// speedup vs baseline: 1.3643x; 1.1366x over previous
#include <cuda_runtime.h>
#include <stdint.h>

// PHM embedding: out[tok, q*256 + j] = sum_k a[k,p,q] * s[k,i,j]
//   t = input[tok]; p = t / 12565; i = t % 12565
//   a: [4,4,4] (k,p,q) f32 ; s: [4,12565,256] f32 ; out: [16384,1024] f32
//
// R10 config (MLP-8: 8 tok x 32 lanes; cache_hint evict_first stores --
// the only store mode that also removes the inter-replay drain) with
// occupancy forced to 5 blocks/SM (<=51 regs): keeps the 8 front-batched
// LDG.128 while raising resident warps 24 -> 40/SM.

static constexpr int N_ROWS = 12565;   // VOCAB_PAD / 4
static constexpr int EV4    = 64;      // 256 f32 cols / 4 per float4
static constexpr int TOK_PER_BLK = 8;

__device__ __forceinline__ void stg_stream(float4* p, float4 v, uint64_t pol) {
    asm volatile("st.global.L2::cache_hint.v4.f32 [%0], {%1,%2,%3,%4}, %5;"
                 :: "l"(p), "f"(v.x), "f"(v.y), "f"(v.z), "f"(v.w), "l"(pol)
                 : "memory");
}

__global__ void __launch_bounds__(256, 5)
phm_embed_kernel(const int* __restrict__ inp,
                 const float* __restrict__ a,
                 const float4* __restrict__ s,
                 float4* __restrict__ out,
                 int n_tok)
{
    const int lane = threadIdx.x & 31;        // first float4 column
    const int tsub = threadIdx.x >> 5;        // token within block (0..7)
    const int tok  = blockIdx.x * TOK_PER_BLK + tsub;
    if (tok >= n_tok) return;

    const int t = inp[tok];
    const int p = t / N_ROWS;                 // compile-time magic divide
    const int i = t - p * N_ROWS;

    const float4* srow = s + (size_t)i * EV4 + lane;

    // 8 independent loads front-batched: 4 k-rows x 2 column vectors.
    float4 svA0 = __ldg(srow + 0 * N_ROWS * EV4);
    float4 svB0 = __ldg(srow + 0 * N_ROWS * EV4 + 32);
    float4 svA1 = __ldg(srow + 1 * N_ROWS * EV4);
    float4 svB1 = __ldg(srow + 1 * N_ROWS * EV4 + 32);
    float4 svA2 = __ldg(srow + 2 * N_ROWS * EV4);
    float4 svB2 = __ldg(srow + 2 * N_ROWS * EV4 + 32);
    float4 svA3 = __ldg(srow + 3 * N_ROWS * EV4);
    float4 svB3 = __ldg(srow + 3 * N_ROWS * EV4 + 32);

    uint64_t pol_stream;
    asm volatile("createpolicy.fractional.L2::evict_first.b64 %0, 1.0;"
                 : "=l"(pol_stream));

    // a[k,p,q] = a[k*16 + p*4 + q]; broadcast loads, L1-resident.
    const float* ap = a + p * 4;

    float4* outp = out + (size_t)tok * 256 + lane;   // 256 float4 per token

#pragma unroll
    for (int q = 0; q < 4; q++) {
        const float c0 = __ldg(&ap[ 0 + q]);
        const float c1 = __ldg(&ap[16 + q]);
        const float c2 = __ldg(&ap[32 + q]);
        const float c3 = __ldg(&ap[48 + q]);

        float4 oA, oB;
        oA.x = c0 * svA0.x + c1 * svA1.x + c2 * svA2.x + c3 * svA3.x;
        oA.y = c0 * svA0.y + c1 * svA1.y + c2 * svA2.y + c3 * svA3.y;
        oA.z = c0 * svA0.z + c1 * svA1.z + c2 * svA2.z + c3 * svA3.z;
        oA.w = c0 * svA0.w + c1 * svA1.w + c2 * svA2.w + c3 * svA3.w;

        oB.x = c0 * svB0.x + c1 * svB1.x + c2 * svB2.x + c3 * svB3.x;
        oB.y = c0 * svB0.y + c1 * svB1.y + c2 * svB2.y + c3 * svB3.y;
        oB.z = c0 * svB0.z + c1 * svB1.z + c2 * svB2.z + c3 * svB3.z;
        oB.w = c0 * svB0.w + c1 * svB1.w + c2 * svB2.w + c3 * svB3.w;

        stg_stream(outp + q * EV4,      oA, pol_stream);
        stg_stream(outp + q * EV4 + 32, oB, pol_stream);
    }
}

extern "C" void kernel_launch(void* const* d_in, const int* in_sizes, int n_in,
                              void* d_out, int out_size)
{
    const int*    inp = (const int*)d_in[0];    // [8,2048] int32
    const float*  a   = (const float*)d_in[1];  // [4,4,4]
    const float4* s   = (const float4*)d_in[2]; // [4,12565,256] f32 as float4
    float4*       out = (float4*)d_out;

    const int n_tok = in_sizes[0];              // 16384
    const int grid  = (n_tok + TOK_PER_BLK - 1) / TOK_PER_BLK;
    phm_embed_kernel<<<grid, 256>>>(inp, a, s, out, n_tok);
}